// round 15
// baseline (speedup 1.0000x reference)
#include <cuda_runtime.h>
#include <cuda_bf16.h>
#include <cuda_fp16.h>
#include <cstdint>

#define NN 50000
#define EE 800000
#define KPAD 136   // bf16 elems per SMEM row (272B) -> conflict-free fragments

// ---------------- scratch (static device globals) --------------------------
__device__ __half g_Y16[NN * 128]; // post-GEMM, dinv[row]-scaled features (fp16)
__device__ __half g_H16[NN * 128]; // layer output (post-bias, fp16)
__device__ float  g_dinv[NN];
__device__ int    g_deg[NN];       // edge-only degree; zeroed by scan_final for next replay
__device__ int    g_epos[EE];      // per-edge slot within its dst row (from count_k)
__device__ int    g_rowptr[NN + 1];
__device__ int    g_csrc[EE];
__device__ int    g_bsum[64];
// pre-split, pre-transposed weights: [N][K=128] bf16, hi + lo parts
__device__ __nv_bfloat16 g_W1h[128 * 128], g_W1l[128 * 128];
__device__ __nv_bfloat16 g_W2h[128 * 128], g_W2l[128 * 128];
__device__ __nv_bfloat16 g_W3h[64 * 128],  g_W3l[64 * 128];

// ---------------- preprocessing (main stream) --------------------------------

// degree count; also records each edge's slot within its destination row
__global__ void count_k(const int* __restrict__ ei, int E) {
    int e = blockIdx.x * blockDim.x + threadIdx.x;
    if (e < E) {
        int pos = atomicAdd(&g_deg[ei[E + e]], 1);
        g_epos[e] = pos;
    }
}

__global__ void scan_partial_k(int n) {
    __shared__ int sm[32];
    int tid = threadIdx.x;
    int i = blockIdx.x * 1024 + tid;
    int v = 0;
    if (i < n) {
        v = g_deg[i];
        g_dinv[i] = rsqrtf((float)(v + 1));
    }
    int vv = v;
    #pragma unroll
    for (int o = 16; o > 0; o >>= 1) vv += __shfl_down_sync(0xffffffffu, vv, o);
    int lane = tid & 31, wid = tid >> 5;
    if (lane == 0) sm[wid] = vv;
    __syncthreads();
    if (wid == 0) {
        vv = sm[lane];
        #pragma unroll
        for (int o = 16; o > 0; o >>= 1) vv += __shfl_down_sync(0xffffffffu, vv, o);
        if (lane == 0) g_bsum[blockIdx.x] = vv;
    }
}

__global__ void scan_final_k(int n, int nbS) {
    __shared__ int sm[1024];
    __shared__ int s_off;
    int tid = threadIdx.x;
    int bid = blockIdx.x;
    int i = bid * 1024 + tid;

    if (tid < 32) {
        int a = (tid      < bid) ? g_bsum[tid]      : 0;
        int b = (tid + 32 < bid) ? g_bsum[tid + 32] : 0;
        int s = a + b;
        #pragma unroll
        for (int o = 16; o > 0; o >>= 1) s += __shfl_down_sync(0xffffffffu, s, o);
        if (tid == 0) s_off = s;
    }

    int v = 0;
    if (i < n) {
        v = g_deg[i];
        g_deg[i] = 0;                          // reset for next graph replay
    }
    sm[tid] = v;
    __syncthreads();
    #pragma unroll
    for (int off = 1; off < 1024; off <<= 1) {
        int t = 0;
        if (tid >= off) t = sm[tid - off];
        __syncthreads();
        if (tid >= off) sm[tid] += t;
        __syncthreads();
    }
    int incl = sm[tid];
    if (i < n) {
        g_rowptr[i] = s_off + incl - v;
        if (i == n - 1) g_rowptr[n] = s_off + incl;
    }
}

// atomic-free fill: slot was precomputed in count_k
__global__ void fill_k(const int* __restrict__ ei, int E) {
    int e = blockIdx.x * blockDim.x + threadIdx.x;
    if (e < E) {
        int s = ei[e];
        int d = ei[E + e];
        g_csrc[g_rowptr[d] + g_epos[e]] = s;
    }
}

// ---------------- weight conversion (stream B) -------------------------------
__device__ __forceinline__ void conv_one(const float* W, __nv_bfloat16* Wh,
                                         __nv_bfloat16* Wl, int F, int idx) {
    int nn = idx >> 7, k = idx & 127;
    float v = W[k * F + nn];
    __nv_bfloat16 h = __float2bfloat16(v);
    __nv_bfloat16 l = __float2bfloat16(v - __bfloat162float(h));
    Wh[nn * 128 + k] = h;
    Wl[nn * 128 + k] = l;
}

__global__ void convW_all_k(const float* __restrict__ W1,
                            const float* __restrict__ W2,
                            const float* __restrict__ W3) {
    int idx = blockIdx.x * blockDim.x + threadIdx.x;
    if (idx < 16384)       conv_one(W1, g_W1h, g_W1l, 128, idx);
    else if (idx < 32768)  conv_one(W2, g_W2h, g_W2l, 128, idx - 16384);
    else if (idx < 40960)  conv_one(W3, g_W3h, g_W3l, 64,  idx - 32768);
}

// ---------------- tensor-core GEMM ------------------------------------------
// Y16[n,F] = half((relu?(A[n,128]) @ W[128,F]) * dinv[row]),  bf16x3 split.
// A may be fp32 (layer 1) or fp16 (layers 2,3; split hi/lo is exact for fp16).

__device__ __forceinline__ __half2 H2u(unsigned u) {
    return *reinterpret_cast<__half2*>(&u);
}

__device__ __forceinline__ unsigned packbf(float a, float b) {
    __nv_bfloat162 p = __floats2bfloat162_rn(a, b);
    return *reinterpret_cast<unsigned*>(&p);
}

__device__ __forceinline__ void mma_bf16(float* c,
                                         unsigned a0, unsigned a1, unsigned a2, unsigned a3,
                                         unsigned b0, unsigned b1) {
    asm volatile(
        "mma.sync.aligned.m16n8k16.row.col.f32.bf16.bf16.f32 "
        "{%0,%1,%2,%3}, {%4,%5,%6,%7}, {%8,%9}, {%0,%1,%2,%3};"
        : "+f"(c[0]), "+f"(c[1]), "+f"(c[2]), "+f"(c[3])
        : "r"(a0), "r"(a1), "r"(a2), "r"(a3), "r"(b0), "r"(b1));
}

template <int F, bool RELU, typename AT>
__global__ __launch_bounds__(256)
void gemm_tc(const AT* __restrict__ A,
             const __nv_bfloat16* __restrict__ Wh,
             const __nv_bfloat16* __restrict__ Wl, int n) {
    extern __shared__ unsigned char smraw[];
    __nv_bfloat16* sWh = (__nv_bfloat16*)smraw;        // F * KPAD
    __nv_bfloat16* sWl = sWh + F * KPAD;
    __nv_bfloat16* sAh = sWl + F * KPAD;               // 128 * KPAD
    __nv_bfloat16* sAl = sAh + 128 * KPAD;

    const int NT = F / 16;
    int tid = threadIdx.x;
    int wid = tid >> 5, lane = tid & 31;
    int g = lane >> 2, t = lane & 3;
    int wm = wid >> 1;
    int wn = wid & 1;
    int arow = wm * 32;
    int bcol0 = wn * (F / 2);

    {
        const unsigned* gwh = (const unsigned*)Wh;
        const unsigned* gwl = (const unsigned*)Wl;
        for (int i = tid; i < F * 64; i += 256) {
            int r = i >> 6, c = i & 63;
            ((unsigned*)(sWh + r * KPAD))[c] = gwh[i];
            ((unsigned*)(sWl + r * KPAD))[c] = gwl[i];
        }
    }

    int ntiles = (n + 127) >> 7;
    for (int tile = blockIdx.x; tile < ntiles; tile += gridDim.x) {
        __syncthreads();
        int r0 = tile * 128;

        for (int i = tid; i < 4096; i += 256) {
            int r = i >> 5, c4 = i & 31;
            int row = r0 + r;
            float4 v = make_float4(0.f, 0.f, 0.f, 0.f);
            if (row < n) {
                if constexpr (sizeof(AT) == 2) {
                    uint2 hv = *(const uint2*)(A + (size_t)row * 128 + c4 * 4);
                    float2 f01 = __half22float2(H2u(hv.x));
                    float2 f23 = __half22float2(H2u(hv.y));
                    v = make_float4(f01.x, f01.y, f23.x, f23.y);
                } else {
                    v = *(const float4*)((const float*)A + (size_t)row * 128 + c4 * 4);
                }
            }
            if (RELU) {
                v.x = fmaxf(v.x, 0.f); v.y = fmaxf(v.y, 0.f);
                v.z = fmaxf(v.z, 0.f); v.w = fmaxf(v.w, 0.f);
            }
            __nv_bfloat16 h0 = __float2bfloat16(v.x), h1 = __float2bfloat16(v.y);
            __nv_bfloat16 h2 = __float2bfloat16(v.z), h3 = __float2bfloat16(v.w);
            float l0 = v.x - __bfloat162float(h0), l1 = v.y - __bfloat162float(h1);
            float l2 = v.z - __bfloat162float(h2), l3 = v.w - __bfloat162float(h3);
            unsigned h01, h23;
            { __nv_bfloat162 p0 = {h0, h1}; h01 = *reinterpret_cast<unsigned*>(&p0);
              __nv_bfloat162 p1 = {h2, h3}; h23 = *reinterpret_cast<unsigned*>(&p1); }
            unsigned l01 = packbf(l0, l1), l23 = packbf(l2, l3);
            *reinterpret_cast<uint2*>(sAh + r * KPAD + c4 * 4) = make_uint2(h01, h23);
            *reinterpret_cast<uint2*>(sAl + r * KPAD + c4 * 4) = make_uint2(l01, l23);
        }
        __syncthreads();

        float acc[2][NT][4];
        #pragma unroll
        for (int rb = 0; rb < 2; rb++)
            #pragma unroll
            for (int j = 0; j < NT; j++) {
                acc[rb][j][0] = 0.f; acc[rb][j][1] = 0.f;
                acc[rb][j][2] = 0.f; acc[rb][j][3] = 0.f;
            }

        #pragma unroll
        for (int kk = 0; kk < 128; kk += 16) {
            unsigned ah[2][4], al[2][4];
            #pragma unroll
            for (int rb = 0; rb < 2; rb++) {
                int br = arow + rb * 16;
                ah[rb][0] = *(const unsigned*)(sAh + (br + g)     * KPAD + kk + 2 * t);
                ah[rb][1] = *(const unsigned*)(sAh + (br + g + 8) * KPAD + kk + 2 * t);
                ah[rb][2] = *(const unsigned*)(sAh + (br + g)     * KPAD + kk + 8 + 2 * t);
                ah[rb][3] = *(const unsigned*)(sAh + (br + g + 8) * KPAD + kk + 8 + 2 * t);
                al[rb][0] = *(const unsigned*)(sAl + (br + g)     * KPAD + kk + 2 * t);
                al[rb][1] = *(const unsigned*)(sAl + (br + g + 8) * KPAD + kk + 2 * t);
                al[rb][2] = *(const unsigned*)(sAl + (br + g)     * KPAD + kk + 8 + 2 * t);
                al[rb][3] = *(const unsigned*)(sAl + (br + g + 8) * KPAD + kk + 8 + 2 * t);
            }
            #pragma unroll
            for (int j = 0; j < NT; j++) {
                int bn = bcol0 + j * 8 + g;
                unsigned b0h = *(const unsigned*)(sWh + bn * KPAD + kk + 2 * t);
                unsigned b1h = *(const unsigned*)(sWh + bn * KPAD + kk + 8 + 2 * t);
                unsigned b0l = *(const unsigned*)(sWl + bn * KPAD + kk + 2 * t);
                unsigned b1l = *(const unsigned*)(sWl + bn * KPAD + kk + 8 + 2 * t);
                #pragma unroll
                for (int rb = 0; rb < 2; rb++) {
                    mma_bf16(acc[rb][j], ah[rb][0], ah[rb][1], ah[rb][2], ah[rb][3], b0h, b1h);
                    mma_bf16(acc[rb][j], ah[rb][0], ah[rb][1], ah[rb][2], ah[rb][3], b0l, b1l);
                    mma_bf16(acc[rb][j], al[rb][0], al[rb][1], al[rb][2], al[rb][3], b0h, b1h);
                }
            }
        }

        // epilogue: scale by dinv[row], write Y as fp16
        #pragma unroll
        for (int rb = 0; rb < 2; rb++) {
            int row0 = r0 + arow + rb * 16 + g;
            int row1 = row0 + 8;
            float d0 = (row0 < n) ? g_dinv[row0] : 0.f;
            float d1 = (row1 < n) ? g_dinv[row1] : 0.f;
            #pragma unroll
            for (int j = 0; j < NT; j++) {
                int col = bcol0 + j * 8 + 2 * t;
                if (row0 < n) {
                    __half2 p = __floats2half2_rn(acc[rb][j][0] * d0, acc[rb][j][1] * d0);
                    *(__half2*)(g_Y16 + (size_t)row0 * F + col) = p;
                }
                if (row1 < n) {
                    __half2 p = __floats2half2_rn(acc[rb][j][2] * d1, acc[rb][j][3] * d1);
                    *(__half2*)(g_Y16 + (size_t)row1 * F + col) = p;
                }
            }
        }
    }
}

// ---------------- aggregation ------------------------------------------------
// out[i] = dinv[i]*(Y[i] + sum Y[src]) + b
// fp16 gather; 4 staged rows reduced by an fp16 pairwise tree, root accumulated
// fp32. Tail/self-loop exact fp32. Output fp16 (layers 1,2) or fp32 (layer 3).
__device__ __forceinline__ __half2 H2(unsigned u) {
    return *reinterpret_cast<__half2*>(&u);
}

__device__ __forceinline__ void acc8(float* a, uint4 r) {
    float2 f0 = __half22float2(H2(r.x));
    float2 f1 = __half22float2(H2(r.y));
    float2 f2 = __half22float2(H2(r.z));
    float2 f3 = __half22float2(H2(r.w));
    a[0] += f0.x; a[1] += f0.y; a[2] += f1.x; a[3] += f1.y;
    a[4] += f2.x; a[5] += f2.y; a[6] += f3.x; a[7] += f3.y;
}

template <int F, typename OT>
__global__ __launch_bounds__(256)
void agg_k(const float* __restrict__ bias, OT* __restrict__ out, int n) {
    const int L = F / 8;                               // lanes per node (16 / 8)
    int lane = threadIdx.x & (L - 1);
    int node = (blockIdx.x * blockDim.x + threadIdx.x) / L;
    if (node >= n) return;

    unsigned mask = ((L == 32) ? 0xffffffffu
                               : (((1u << L) - 1u) << (((threadIdx.x & 31) / L) * L)));

    int s = g_rowptr[node];
    int e = g_rowptr[node + 1];

    const __half* Yb = g_Y16;                          // 32-bit offsets suffice
    unsigned loff = lane * 8;

    float a[8];
    {
        uint4 r = *(const uint4*)(Yb + (unsigned)node * F + loff);  // self loop
        #pragma unroll
        for (int q = 0; q < 8; q++) a[q] = 0.f;
        acc8(a, r);
    }

    for (int base = s; base < e; base += L) {
        int idx = base + lane;
        int v = (idx < e) ? g_csrc[idx] : 0;
        int cnt = min(L, e - base);
        int tt = 0;
        for (; tt + 4 <= cnt; tt += 4) {
            unsigned s0 = (unsigned)__shfl_sync(mask, v, tt,     L) * F + loff;
            unsigned s1 = (unsigned)__shfl_sync(mask, v, tt + 1, L) * F + loff;
            unsigned s2 = (unsigned)__shfl_sync(mask, v, tt + 2, L) * F + loff;
            unsigned s3 = (unsigned)__shfl_sync(mask, v, tt + 3, L) * F + loff;
            uint4 r0 = *(const uint4*)(Yb + s0);
            uint4 r1 = *(const uint4*)(Yb + s1);
            uint4 r2 = *(const uint4*)(Yb + s2);
            uint4 r3 = *(const uint4*)(Yb + s3);
            // fp16 pairwise tree per half2 component, fp32 accumulate of root
            #pragma unroll
            for (int c = 0; c < 4; c++) {
                __half2 t01 = __hadd2(H2((&r0.x)[c]), H2((&r1.x)[c]));
                __half2 t23 = __hadd2(H2((&r2.x)[c]), H2((&r3.x)[c]));
                __half2 tr  = __hadd2(t01, t23);
                float2 f = __half22float2(tr);
                a[c * 2 + 0] += f.x;
                a[c * 2 + 1] += f.y;
            }
        }
        for (; tt < cnt; tt++) {
            unsigned sc = (unsigned)__shfl_sync(mask, v, tt, L) * F + loff;
            uint4 r = *(const uint4*)(Yb + sc);
            acc8(a, r);
        }
    }

    float d = g_dinv[node];
    float4 b0 = *(const float4*)(bias + loff);
    float4 b1 = *(const float4*)(bias + loff + 4);
    float o[8];
    #pragma unroll
    for (int q = 0; q < 8; q++) o[q] = a[q] * d;
    o[0] += b0.x; o[1] += b0.y; o[2] += b0.z; o[3] += b0.w;
    o[4] += b1.x; o[5] += b1.y; o[6] += b1.z; o[7] += b1.w;

    if constexpr (sizeof(OT) == 2) {
        __half2 p0 = __floats2half2_rn(o[0], o[1]);
        __half2 p1 = __floats2half2_rn(o[2], o[3]);
        __half2 p2 = __floats2half2_rn(o[4], o[5]);
        __half2 p3 = __floats2half2_rn(o[6], o[7]);
        uint4 w;
        w.x = *reinterpret_cast<unsigned*>(&p0);
        w.y = *reinterpret_cast<unsigned*>(&p1);
        w.z = *reinterpret_cast<unsigned*>(&p2);
        w.w = *reinterpret_cast<unsigned*>(&p3);
        *(uint4*)((__half*)out + (size_t)node * F + loff) = w;
    } else {
        *(float4*)((float*)out + (size_t)node * F + loff)     = make_float4(o[0], o[1], o[2], o[3]);
        *(float4*)((float*)out + (size_t)node * F + loff + 4) = make_float4(o[4], o[5], o[6], o[7]);
    }
}

// ---------------- launch -----------------------------------------------------

extern "C" void kernel_launch(void* const* d_in, const int* in_sizes, int n_in,
                              void* d_out, int out_size) {
    const float* x  = (const float*)d_in[0];
    const int*   ei = (const int*)d_in[1];   // int32
    const float* W1 = (const float*)d_in[2];
    const float* b1 = (const float*)d_in[3];
    const float* W2 = (const float*)d_in[4];
    const float* b2 = (const float*)d_in[5];
    const float* W3 = (const float*)d_in[6];
    const float* b3 = (const float*)d_in[7];
    float* out = (float*)d_out;

    __half* hH = nullptr;
    cudaGetSymbolAddress((void**)&hH, g_H16);
    __nv_bfloat16 *w1h, *w1l, *w2h, *w2l, *w3h, *w3l;
    cudaGetSymbolAddress((void**)&w1h, g_W1h);
    cudaGetSymbolAddress((void**)&w1l, g_W1l);
    cudaGetSymbolAddress((void**)&w2h, g_W2h);
    cudaGetSymbolAddress((void**)&w2l, g_W2l);
    cudaGetSymbolAddress((void**)&w3h, g_W3h);
    cudaGetSymbolAddress((void**)&w3l, g_W3l);

    int n = in_sizes[0] / 128;
    int E = in_sizes[1] / 2;

    const int SMEM128 = 4 * KPAD * (128 + 128);  // 139264 B
    const int SMEM64  = 4 * KPAD * (64  + 128);  // 104448 B
    cudaFuncSetAttribute(gemm_tc<128, false, float>,  cudaFuncAttributeMaxDynamicSharedMemorySize, SMEM128);
    cudaFuncSetAttribute(gemm_tc<128, true,  __half>, cudaFuncAttributeMaxDynamicSharedMemorySize, SMEM128);
    cudaFuncSetAttribute(gemm_tc<64,  true,  __half>, cudaFuncAttributeMaxDynamicSharedMemorySize, SMEM64);

    // side stream + events (created once on the un-captured correctness call)
    static cudaStream_t sB = nullptr;
    static cudaEvent_t  evF = nullptr, evD = nullptr, evJ = nullptr;
    if (sB == nullptr) {
        cudaStreamCreateWithFlags(&sB, cudaStreamNonBlocking);
        cudaEventCreateWithFlags(&evF, cudaEventDisableTiming);
        cudaEventCreateWithFlags(&evD, cudaEventDisableTiming);
        cudaEventCreateWithFlags(&evJ, cudaEventDisableTiming);
    }

    int nbE = (E + 255) / 256;
    int nbS = (n + 1023) / 1024;   // 49 <= 64

    // ---- fork ----
    cudaEventRecord(evF, 0);
    cudaStreamWaitEvent(sB, evF, 0);

    // main stream: CSR chain (critical path for agg1)
    count_k<<<nbE, 256>>>(ei, E);               // + epos
    scan_partial_k<<<nbS, 1024>>>(n);           // produces dinv
    cudaEventRecord(evD, 0);                    // dinv ready
    scan_final_k<<<nbS, 1024>>>(n, nbS);
    fill_k<<<nbE, 256>>>(ei, E);                // atomic-free

    // stream B: weights + gemm1 (epilogue needs dinv -> waits evD)
    convW_all_k<<<160, 256, 0, sB>>>(W1, W2, W3);
    cudaStreamWaitEvent(sB, evD, 0);
    gemm_tc<128, false, float><<<148, 256, SMEM128, sB>>>(x, w1h, w1l, n);
    cudaEventRecord(evJ, sB);

    // ---- join ----
    cudaStreamWaitEvent(0, evJ, 0);

    int gAgg128 = ((n * 16) + 255) / 256;   // L=16 lanes per node
    int gAgg64  = ((n * 8)  + 255) / 256;   // L=8

    agg_k<128, __half><<<gAgg128, 256>>>(b1, hH, n);

    gemm_tc<128, true, __half><<<148, 256, SMEM128>>>(hH, w2h, w2l, n);
    agg_k<128, __half><<<gAgg128, 256>>>(b2, hH, n);

    gemm_tc<64, true, __half><<<148, 256, SMEM64>>>(hH, w3h, w3l, n);
    agg_k<64, float><<<gAgg64, 256>>>(b3, out, n);
}

// round 16
// speedup vs baseline: 1.3865x; 1.3865x over previous
#include <cuda_runtime.h>
#include <cuda_bf16.h>
#include <cuda_fp16.h>
#include <cstdint>

#define NN 50000
#define EE 800000
#define KPAD 136   // bf16 elems per SMEM row (272B) -> conflict-free fragments

// ---------------- scratch (static device globals) --------------------------
__device__ __half g_Y16[NN * 128]; // post-GEMM, dinv[row]-scaled features (fp16)
__device__ float  g_H[NN * 128];   // layer output (post-bias, fp32)
__device__ float  g_dinv[NN];
__device__ int    g_deg[NN];       // edge-only degree; zeroed by scan_final for next replay
__device__ int    g_epos[EE];      // per-edge slot within its dst row (from count_k)
__device__ int    g_rowptr[NN + 1];
__device__ int    g_csrc[EE];
__device__ int    g_bsum[64];
// pre-split, pre-transposed weights: [N][K=128] bf16, hi + lo parts
__device__ __nv_bfloat16 g_W1h[128 * 128], g_W1l[128 * 128];
__device__ __nv_bfloat16 g_W2h[128 * 128], g_W2l[128 * 128];
__device__ __nv_bfloat16 g_W3h[64 * 128],  g_W3l[64 * 128];

// ---------------- preprocessing (main stream) --------------------------------

// degree count; also records each edge's slot within its destination row
__global__ void count_k(const int* __restrict__ ei, int E) {
    int e = blockIdx.x * blockDim.x + threadIdx.x;
    if (e < E) {
        int pos = atomicAdd(&g_deg[ei[E + e]], 1);
        g_epos[e] = pos;
    }
}

__global__ void scan_partial_k(int n) {
    __shared__ int sm[32];
    int tid = threadIdx.x;
    int i = blockIdx.x * 1024 + tid;
    int v = 0;
    if (i < n) {
        v = g_deg[i];
        g_dinv[i] = rsqrtf((float)(v + 1));
    }
    int vv = v;
    #pragma unroll
    for (int o = 16; o > 0; o >>= 1) vv += __shfl_down_sync(0xffffffffu, vv, o);
    int lane = tid & 31, wid = tid >> 5;
    if (lane == 0) sm[wid] = vv;
    __syncthreads();
    if (wid == 0) {
        vv = sm[lane];
        #pragma unroll
        for (int o = 16; o > 0; o >>= 1) vv += __shfl_down_sync(0xffffffffu, vv, o);
        if (lane == 0) g_bsum[blockIdx.x] = vv;
    }
}

__global__ void scan_final_k(int n, int nbS) {
    __shared__ int sm[1024];
    __shared__ int s_off;
    int tid = threadIdx.x;
    int bid = blockIdx.x;
    int i = bid * 1024 + tid;

    if (tid < 32) {
        int a = (tid      < bid) ? g_bsum[tid]      : 0;
        int b = (tid + 32 < bid) ? g_bsum[tid + 32] : 0;
        int s = a + b;
        #pragma unroll
        for (int o = 16; o > 0; o >>= 1) s += __shfl_down_sync(0xffffffffu, s, o);
        if (tid == 0) s_off = s;
    }

    int v = 0;
    if (i < n) {
        v = g_deg[i];
        g_deg[i] = 0;                          // reset for next graph replay
    }
    sm[tid] = v;
    __syncthreads();
    #pragma unroll
    for (int off = 1; off < 1024; off <<= 1) {
        int t = 0;
        if (tid >= off) t = sm[tid - off];
        __syncthreads();
        if (tid >= off) sm[tid] += t;
        __syncthreads();
    }
    int incl = sm[tid];
    if (i < n) {
        g_rowptr[i] = s_off + incl - v;
        if (i == n - 1) g_rowptr[n] = s_off + incl;
    }
}

// atomic-free fill: slot was precomputed in count_k
__global__ void fill_k(const int* __restrict__ ei, int E) {
    int e = blockIdx.x * blockDim.x + threadIdx.x;
    if (e < E) {
        int s = ei[e];
        int d = ei[E + e];
        g_csrc[g_rowptr[d] + g_epos[e]] = s;
    }
}

// ---------------- weight conversion (stream B) -------------------------------
__device__ __forceinline__ void conv_one(const float* W, __nv_bfloat16* Wh,
                                         __nv_bfloat16* Wl, int F, int idx) {
    int nn = idx >> 7, k = idx & 127;
    float v = W[k * F + nn];
    __nv_bfloat16 h = __float2bfloat16(v);
    __nv_bfloat16 l = __float2bfloat16(v - __bfloat162float(h));
    Wh[nn * 128 + k] = h;
    Wl[nn * 128 + k] = l;
}

__global__ void convW_all_k(const float* __restrict__ W1,
                            const float* __restrict__ W2,
                            const float* __restrict__ W3) {
    int idx = blockIdx.x * blockDim.x + threadIdx.x;
    if (idx < 16384)       conv_one(W1, g_W1h, g_W1l, 128, idx);
    else if (idx < 32768)  conv_one(W2, g_W2h, g_W2l, 128, idx - 16384);
    else if (idx < 40960)  conv_one(W3, g_W3h, g_W3l, 64,  idx - 32768);
}

// ---------------- tensor-core GEMM ------------------------------------------
// Y16[n,F] = half((relu?(A[n,128]) @ W[128,F]) * dinv[row]),  bf16x3 split.

__device__ __forceinline__ unsigned packbf(float a, float b) {
    __nv_bfloat162 p = __floats2bfloat162_rn(a, b);
    return *reinterpret_cast<unsigned*>(&p);
}

__device__ __forceinline__ void mma_bf16(float* c,
                                         unsigned a0, unsigned a1, unsigned a2, unsigned a3,
                                         unsigned b0, unsigned b1) {
    asm volatile(
        "mma.sync.aligned.m16n8k16.row.col.f32.bf16.bf16.f32 "
        "{%0,%1,%2,%3}, {%4,%5,%6,%7}, {%8,%9}, {%0,%1,%2,%3};"
        : "+f"(c[0]), "+f"(c[1]), "+f"(c[2]), "+f"(c[3])
        : "r"(a0), "r"(a1), "r"(a2), "r"(a3), "r"(b0), "r"(b1));
}

template <int F, bool RELU>
__global__ __launch_bounds__(256)
void gemm_tc(const float* __restrict__ A,
             const __nv_bfloat16* __restrict__ Wh,
             const __nv_bfloat16* __restrict__ Wl, int n) {
    extern __shared__ unsigned char smraw[];
    __nv_bfloat16* sWh = (__nv_bfloat16*)smraw;        // F * KPAD
    __nv_bfloat16* sWl = sWh + F * KPAD;
    __nv_bfloat16* sAh = sWl + F * KPAD;               // 128 * KPAD
    __nv_bfloat16* sAl = sAh + 128 * KPAD;

    const int NT = F / 16;
    int tid = threadIdx.x;
    int wid = tid >> 5, lane = tid & 31;
    int g = lane >> 2, t = lane & 3;
    int wm = wid >> 1;
    int wn = wid & 1;
    int arow = wm * 32;
    int bcol0 = wn * (F / 2);

    {
        const unsigned* gwh = (const unsigned*)Wh;
        const unsigned* gwl = (const unsigned*)Wl;
        for (int i = tid; i < F * 64; i += 256) {
            int r = i >> 6, c = i & 63;
            ((unsigned*)(sWh + r * KPAD))[c] = gwh[i];
            ((unsigned*)(sWl + r * KPAD))[c] = gwl[i];
        }
    }

    int ntiles = (n + 127) >> 7;
    for (int tile = blockIdx.x; tile < ntiles; tile += gridDim.x) {
        __syncthreads();
        int r0 = tile * 128;

        for (int i = tid; i < 4096; i += 256) {
            int r = i >> 5, c4 = i & 31;
            int row = r0 + r;
            float4 v = make_float4(0.f, 0.f, 0.f, 0.f);
            if (row < n) v = *(const float4*)(A + (size_t)row * 128 + c4 * 4);
            if (RELU) {
                v.x = fmaxf(v.x, 0.f); v.y = fmaxf(v.y, 0.f);
                v.z = fmaxf(v.z, 0.f); v.w = fmaxf(v.w, 0.f);
            }
            __nv_bfloat16 h0 = __float2bfloat16(v.x), h1 = __float2bfloat16(v.y);
            __nv_bfloat16 h2 = __float2bfloat16(v.z), h3 = __float2bfloat16(v.w);
            float l0 = v.x - __bfloat162float(h0), l1 = v.y - __bfloat162float(h1);
            float l2 = v.z - __bfloat162float(h2), l3 = v.w - __bfloat162float(h3);
            unsigned h01, h23;
            { __nv_bfloat162 p0 = {h0, h1}; h01 = *reinterpret_cast<unsigned*>(&p0);
              __nv_bfloat162 p1 = {h2, h3}; h23 = *reinterpret_cast<unsigned*>(&p1); }
            unsigned l01 = packbf(l0, l1), l23 = packbf(l2, l3);
            *reinterpret_cast<uint2*>(sAh + r * KPAD + c4 * 4) = make_uint2(h01, h23);
            *reinterpret_cast<uint2*>(sAl + r * KPAD + c4 * 4) = make_uint2(l01, l23);
        }
        __syncthreads();

        float acc[2][NT][4];
        #pragma unroll
        for (int rb = 0; rb < 2; rb++)
            #pragma unroll
            for (int j = 0; j < NT; j++) {
                acc[rb][j][0] = 0.f; acc[rb][j][1] = 0.f;
                acc[rb][j][2] = 0.f; acc[rb][j][3] = 0.f;
            }

        #pragma unroll
        for (int kk = 0; kk < 128; kk += 16) {
            unsigned ah[2][4], al[2][4];
            #pragma unroll
            for (int rb = 0; rb < 2; rb++) {
                int br = arow + rb * 16;
                ah[rb][0] = *(const unsigned*)(sAh + (br + g)     * KPAD + kk + 2 * t);
                ah[rb][1] = *(const unsigned*)(sAh + (br + g + 8) * KPAD + kk + 2 * t);
                ah[rb][2] = *(const unsigned*)(sAh + (br + g)     * KPAD + kk + 8 + 2 * t);
                ah[rb][3] = *(const unsigned*)(sAh + (br + g + 8) * KPAD + kk + 8 + 2 * t);
                al[rb][0] = *(const unsigned*)(sAl + (br + g)     * KPAD + kk + 2 * t);
                al[rb][1] = *(const unsigned*)(sAl + (br + g + 8) * KPAD + kk + 2 * t);
                al[rb][2] = *(const unsigned*)(sAl + (br + g)     * KPAD + kk + 8 + 2 * t);
                al[rb][3] = *(const unsigned*)(sAl + (br + g + 8) * KPAD + kk + 8 + 2 * t);
            }
            #pragma unroll
            for (int j = 0; j < NT; j++) {
                int bn = bcol0 + j * 8 + g;
                unsigned b0h = *(const unsigned*)(sWh + bn * KPAD + kk + 2 * t);
                unsigned b1h = *(const unsigned*)(sWh + bn * KPAD + kk + 8 + 2 * t);
                unsigned b0l = *(const unsigned*)(sWl + bn * KPAD + kk + 2 * t);
                unsigned b1l = *(const unsigned*)(sWl + bn * KPAD + kk + 8 + 2 * t);
                #pragma unroll
                for (int rb = 0; rb < 2; rb++) {
                    mma_bf16(acc[rb][j], ah[rb][0], ah[rb][1], ah[rb][2], ah[rb][3], b0h, b1h);
                    mma_bf16(acc[rb][j], ah[rb][0], ah[rb][1], ah[rb][2], ah[rb][3], b0l, b1l);
                    mma_bf16(acc[rb][j], al[rb][0], al[rb][1], al[rb][2], al[rb][3], b0h, b1h);
                }
            }
        }

        // epilogue: scale by dinv[row], write Y as fp16
        #pragma unroll
        for (int rb = 0; rb < 2; rb++) {
            int row0 = r0 + arow + rb * 16 + g;
            int row1 = row0 + 8;
            float d0 = (row0 < n) ? g_dinv[row0] : 0.f;
            float d1 = (row1 < n) ? g_dinv[row1] : 0.f;
            #pragma unroll
            for (int j = 0; j < NT; j++) {
                int col = bcol0 + j * 8 + 2 * t;
                if (row0 < n) {
                    __half2 p = __floats2half2_rn(acc[rb][j][0] * d0, acc[rb][j][1] * d0);
                    *(__half2*)(g_Y16 + (size_t)row0 * F + col) = p;
                }
                if (row1 < n) {
                    __half2 p = __floats2half2_rn(acc[rb][j][2] * d1, acc[rb][j][3] * d1);
                    *(__half2*)(g_Y16 + (size_t)row1 * F + col) = p;
                }
            }
        }
    }
}

// ---------------- aggregation ------------------------------------------------
// out[i] = dinv[i]*(Y[i] + sum Y[src]) + b
// fp16 gather via read-only path (__ldg); 4 staged rows reduced by an fp16
// pairwise tree, root accumulated fp32. Tail/self-loop exact fp32.
__device__ __forceinline__ __half2 H2(unsigned u) {
    return *reinterpret_cast<__half2*>(&u);
}

__device__ __forceinline__ void acc8(float* a, uint4 r) {
    float2 f0 = __half22float2(H2(r.x));
    float2 f1 = __half22float2(H2(r.y));
    float2 f2 = __half22float2(H2(r.z));
    float2 f3 = __half22float2(H2(r.w));
    a[0] += f0.x; a[1] += f0.y; a[2] += f1.x; a[3] += f1.y;
    a[4] += f2.x; a[5] += f2.y; a[6] += f3.x; a[7] += f3.y;
}

template <int F>
__global__ __launch_bounds__(256)
void agg_k(const float* __restrict__ bias, float* __restrict__ out, int n) {
    const int L = F / 8;                               // lanes per node (16 / 8)
    int lane = threadIdx.x & (L - 1);
    int node = (blockIdx.x * blockDim.x + threadIdx.x) / L;
    if (node >= n) return;

    unsigned mask = ((L == 32) ? 0xffffffffu
                               : (((1u << L) - 1u) << (((threadIdx.x & 31) / L) * L)));

    int s = __ldg(&g_rowptr[node]);
    int e = __ldg(&g_rowptr[node + 1]);

    const __half* Yb = g_Y16;                          // 32-bit offsets suffice
    unsigned loff = lane * 8;

    float a[8];
    {
        uint4 r = __ldg((const uint4*)(Yb + (unsigned)node * F + loff));  // self loop
        #pragma unroll
        for (int q = 0; q < 8; q++) a[q] = 0.f;
        acc8(a, r);
    }

    for (int base = s; base < e; base += L) {
        int idx = base + lane;
        int v = (idx < e) ? __ldg(&g_csrc[idx]) : 0;
        int cnt = min(L, e - base);
        int tt = 0;
        for (; tt + 4 <= cnt; tt += 4) {
            unsigned s0 = (unsigned)__shfl_sync(mask, v, tt,     L) * F + loff;
            unsigned s1 = (unsigned)__shfl_sync(mask, v, tt + 1, L) * F + loff;
            unsigned s2 = (unsigned)__shfl_sync(mask, v, tt + 2, L) * F + loff;
            unsigned s3 = (unsigned)__shfl_sync(mask, v, tt + 3, L) * F + loff;
            uint4 r0 = __ldg((const uint4*)(Yb + s0));
            uint4 r1 = __ldg((const uint4*)(Yb + s1));
            uint4 r2 = __ldg((const uint4*)(Yb + s2));
            uint4 r3 = __ldg((const uint4*)(Yb + s3));
            // fp16 pairwise tree per half2 component, fp32 accumulate of root
            #pragma unroll
            for (int c = 0; c < 4; c++) {
                __half2 t01 = __hadd2(H2((&r0.x)[c]), H2((&r1.x)[c]));
                __half2 t23 = __hadd2(H2((&r2.x)[c]), H2((&r3.x)[c]));
                __half2 tr  = __hadd2(t01, t23);
                float2 f = __half22float2(tr);
                a[c * 2 + 0] += f.x;
                a[c * 2 + 1] += f.y;
            }
        }
        for (; tt < cnt; tt++) {
            unsigned sc = (unsigned)__shfl_sync(mask, v, tt, L) * F + loff;
            uint4 r = __ldg((const uint4*)(Yb + sc));
            acc8(a, r);
        }
    }

    float d = g_dinv[node];
    float4 b0 = *(const float4*)(bias + loff);
    float4 b1 = *(const float4*)(bias + loff + 4);
    float o[8];
    #pragma unroll
    for (int q = 0; q < 8; q++) o[q] = a[q] * d;
    o[0] += b0.x; o[1] += b0.y; o[2] += b0.z; o[3] += b0.w;
    o[4] += b1.x; o[5] += b1.y; o[6] += b1.z; o[7] += b1.w;
    *(float4*)(out + (size_t)node * F + loff)     = make_float4(o[0], o[1], o[2], o[3]);
    *(float4*)(out + (size_t)node * F + loff + 4) = make_float4(o[4], o[5], o[6], o[7]);
}

// ---------------- launch -----------------------------------------------------

extern "C" void kernel_launch(void* const* d_in, const int* in_sizes, int n_in,
                              void* d_out, int out_size) {
    const float* x  = (const float*)d_in[0];
    const int*   ei = (const int*)d_in[1];   // int32
    const float* W1 = (const float*)d_in[2];
    const float* b1 = (const float*)d_in[3];
    const float* W2 = (const float*)d_in[4];
    const float* b2 = (const float*)d_in[5];
    const float* W3 = (const float*)d_in[6];
    const float* b3 = (const float*)d_in[7];
    float* out = (float*)d_out;

    float* hH = nullptr;
    cudaGetSymbolAddress((void**)&hH, g_H);
    __nv_bfloat16 *w1h, *w1l, *w2h, *w2l, *w3h, *w3l;
    cudaGetSymbolAddress((void**)&w1h, g_W1h);
    cudaGetSymbolAddress((void**)&w1l, g_W1l);
    cudaGetSymbolAddress((void**)&w2h, g_W2h);
    cudaGetSymbolAddress((void**)&w2l, g_W2l);
    cudaGetSymbolAddress((void**)&w3h, g_W3h);
    cudaGetSymbolAddress((void**)&w3l, g_W3l);

    int n = in_sizes[0] / 128;
    int E = in_sizes[1] / 2;

    const int SMEM128 = 4 * KPAD * (128 + 128);  // 139264 B
    const int SMEM64  = 4 * KPAD * (64  + 128);  // 104448 B
    cudaFuncSetAttribute(gemm_tc<128, false>, cudaFuncAttributeMaxDynamicSharedMemorySize, SMEM128);
    cudaFuncSetAttribute(gemm_tc<128, true>,  cudaFuncAttributeMaxDynamicSharedMemorySize, SMEM128);
    cudaFuncSetAttribute(gemm_tc<64,  true>,  cudaFuncAttributeMaxDynamicSharedMemorySize, SMEM64);

    // side stream + events (created once on the un-captured correctness call)
    static cudaStream_t sB = nullptr;
    static cudaEvent_t  evF = nullptr, evD = nullptr, evJ = nullptr;
    if (sB == nullptr) {
        cudaStreamCreateWithFlags(&sB, cudaStreamNonBlocking);
        cudaEventCreateWithFlags(&evF, cudaEventDisableTiming);
        cudaEventCreateWithFlags(&evD, cudaEventDisableTiming);
        cudaEventCreateWithFlags(&evJ, cudaEventDisableTiming);
    }

    int nbE = (E + 255) / 256;
    int nbS = (n + 1023) / 1024;   // 49 <= 64

    // ---- fork ----
    cudaEventRecord(evF, 0);
    cudaStreamWaitEvent(sB, evF, 0);

    // main stream: CSR chain (critical path for agg1)
    count_k<<<nbE, 256>>>(ei, E);               // + epos
    scan_partial_k<<<nbS, 1024>>>(n);           // produces dinv
    cudaEventRecord(evD, 0);                    // dinv ready
    scan_final_k<<<nbS, 1024>>>(n, nbS);
    fill_k<<<nbE, 256>>>(ei, E);                // atomic-free

    // stream B: weights + gemm1 (epilogue needs dinv -> waits evD)
    convW_all_k<<<160, 256, 0, sB>>>(W1, W2, W3);
    cudaStreamWaitEvent(sB, evD, 0);
    gemm_tc<128, false><<<148, 256, SMEM128, sB>>>(x, w1h, w1l, n);
    cudaEventRecord(evJ, sB);

    // ---- join ----
    cudaStreamWaitEvent(0, evJ, 0);

    int gAgg128 = ((n * 16) + 255) / 256;   // L=16 lanes per node
    int gAgg64  = ((n * 8)  + 255) / 256;   // L=8

    agg_k<128><<<gAgg128, 256>>>(b1, hH, n);

    gemm_tc<128, true><<<148, 256, SMEM128>>>(hH, w2h, w2l, n);
    agg_k<128><<<gAgg128, 256>>>(b2, hH, n);

    gemm_tc<64, true><<<148, 256, SMEM64>>>(hH, w3h, w3l, n);
    agg_k<64><<<gAgg64, 256>>>(b3, out, n);
}

// round 17
// speedup vs baseline: 1.4062x; 1.0143x over previous
#include <cuda_runtime.h>
#include <cuda_bf16.h>
#include <cuda_fp16.h>
#include <cstdint>

#define NN 50000
#define EE 800000
#define KPAD 136   // bf16 elems per SMEM row (272B) -> conflict-free fragments

// ---------------- scratch (static device globals) --------------------------
__device__ __half g_Y16[NN * 128]; // post-GEMM, dinv[row]-scaled features (fp16)
__device__ float  g_H[NN * 128];   // layer output (post-bias, fp32)
__device__ float  g_dinv[NN];
__device__ int    g_deg[NN];       // edge-only degree; zeroed by scan_final for next replay
__device__ int    g_epos[EE];      // per-edge slot within its dst row (from count_k)
__device__ int    g_rowptr[NN + 1];
__device__ int    g_csrc[EE];
__device__ int    g_bsum[64];
// pre-split, pre-transposed weights: [N][K=128] bf16, hi + lo parts
__device__ __nv_bfloat16 g_W1h[128 * 128], g_W1l[128 * 128];
__device__ __nv_bfloat16 g_W2h[128 * 128], g_W2l[128 * 128];
__device__ __nv_bfloat16 g_W3h[64 * 128],  g_W3l[64 * 128];

// ---------------- preprocessing (main stream) --------------------------------

// degree count; also records each edge's slot within its destination row
__global__ void count_k(const int* __restrict__ ei, int E) {
    int e = blockIdx.x * blockDim.x + threadIdx.x;
    if (e < E) {
        int pos = atomicAdd(&g_deg[ei[E + e]], 1);
        g_epos[e] = pos;
    }
}

__global__ void scan_partial_k(int n) {
    __shared__ int sm[32];
    int tid = threadIdx.x;
    int i = blockIdx.x * 1024 + tid;
    int v = 0;
    if (i < n) {
        v = g_deg[i];
        g_dinv[i] = rsqrtf((float)(v + 1));
    }
    int vv = v;
    #pragma unroll
    for (int o = 16; o > 0; o >>= 1) vv += __shfl_down_sync(0xffffffffu, vv, o);
    int lane = tid & 31, wid = tid >> 5;
    if (lane == 0) sm[wid] = vv;
    __syncthreads();
    if (wid == 0) {
        vv = sm[lane];
        #pragma unroll
        for (int o = 16; o > 0; o >>= 1) vv += __shfl_down_sync(0xffffffffu, vv, o);
        if (lane == 0) g_bsum[blockIdx.x] = vv;
    }
}

__global__ void scan_final_k(int n, int nbS) {
    __shared__ int sm[1024];
    __shared__ int s_off;
    int tid = threadIdx.x;
    int bid = blockIdx.x;
    int i = bid * 1024 + tid;

    if (tid < 32) {
        int a = (tid      < bid) ? g_bsum[tid]      : 0;
        int b = (tid + 32 < bid) ? g_bsum[tid + 32] : 0;
        int s = a + b;
        #pragma unroll
        for (int o = 16; o > 0; o >>= 1) s += __shfl_down_sync(0xffffffffu, s, o);
        if (tid == 0) s_off = s;
    }

    int v = 0;
    if (i < n) {
        v = g_deg[i];
        g_deg[i] = 0;                          // reset for next graph replay
    }
    sm[tid] = v;
    __syncthreads();
    #pragma unroll
    for (int off = 1; off < 1024; off <<= 1) {
        int t = 0;
        if (tid >= off) t = sm[tid - off];
        __syncthreads();
        if (tid >= off) sm[tid] += t;
        __syncthreads();
    }
    int incl = sm[tid];
    if (i < n) {
        g_rowptr[i] = s_off + incl - v;
        if (i == n - 1) g_rowptr[n] = s_off + incl;
    }
}

// atomic-free fill, 2 edges per thread (independent load->store chains)
__global__ void fill_k(const int* __restrict__ ei, int E) {
    int t = blockIdx.x * blockDim.x + threadIdx.x;
    int e0 = t * 2;
    if (e0 + 2 <= E) {
        int2 s = *(const int2*)(ei + e0);
        int2 d = *(const int2*)(ei + E + e0);
        int r0 = __ldg(&g_rowptr[d.x]);
        int r1 = __ldg(&g_rowptr[d.y]);
        int2 p = *(const int2*)(g_epos + e0);
        g_csrc[r0 + p.x] = s.x;
        g_csrc[r1 + p.y] = s.y;
    } else {
        for (int e = e0; e < E; e++) {
            g_csrc[__ldg(&g_rowptr[ei[E + e]]) + __ldg(&g_epos[e])] = ei[e];
        }
    }
}

// ---------------- weight conversion (stream B) -------------------------------
__device__ __forceinline__ void conv_one(const float* W, __nv_bfloat16* Wh,
                                         __nv_bfloat16* Wl, int F, int idx) {
    int nn = idx >> 7, k = idx & 127;
    float v = W[k * F + nn];
    __nv_bfloat16 h = __float2bfloat16(v);
    __nv_bfloat16 l = __float2bfloat16(v - __bfloat162float(h));
    Wh[nn * 128 + k] = h;
    Wl[nn * 128 + k] = l;
}

__global__ void convW_all_k(const float* __restrict__ W1,
                            const float* __restrict__ W2,
                            const float* __restrict__ W3) {
    int idx = blockIdx.x * blockDim.x + threadIdx.x;
    if (idx < 16384)       conv_one(W1, g_W1h, g_W1l, 128, idx);
    else if (idx < 32768)  conv_one(W2, g_W2h, g_W2l, 128, idx - 16384);
    else if (idx < 40960)  conv_one(W3, g_W3h, g_W3l, 64,  idx - 32768);
}

// ---------------- tensor-core GEMM ------------------------------------------
// Y16[n,F] = half((relu?(A[n,128]) @ W[128,F]) * dinv[row]),  bf16x3 split.

__device__ __forceinline__ unsigned packbf(float a, float b) {
    __nv_bfloat162 p = __floats2bfloat162_rn(a, b);
    return *reinterpret_cast<unsigned*>(&p);
}

__device__ __forceinline__ void mma_bf16(float* c,
                                         unsigned a0, unsigned a1, unsigned a2, unsigned a3,
                                         unsigned b0, unsigned b1) {
    asm volatile(
        "mma.sync.aligned.m16n8k16.row.col.f32.bf16.bf16.f32 "
        "{%0,%1,%2,%3}, {%4,%5,%6,%7}, {%8,%9}, {%0,%1,%2,%3};"
        : "+f"(c[0]), "+f"(c[1]), "+f"(c[2]), "+f"(c[3])
        : "r"(a0), "r"(a1), "r"(a2), "r"(a3), "r"(b0), "r"(b1));
}

template <int F, bool RELU>
__global__ __launch_bounds__(256)
void gemm_tc(const float* __restrict__ A,
             const __nv_bfloat16* __restrict__ Wh,
             const __nv_bfloat16* __restrict__ Wl, int n) {
    extern __shared__ unsigned char smraw[];
    __nv_bfloat16* sWh = (__nv_bfloat16*)smraw;        // F * KPAD
    __nv_bfloat16* sWl = sWh + F * KPAD;
    __nv_bfloat16* sAh = sWl + F * KPAD;               // 128 * KPAD
    __nv_bfloat16* sAl = sAh + 128 * KPAD;

    const int NT = F / 16;
    int tid = threadIdx.x;
    int wid = tid >> 5, lane = tid & 31;
    int g = lane >> 2, t = lane & 3;
    int wm = wid >> 1;
    int wn = wid & 1;
    int arow = wm * 32;
    int bcol0 = wn * (F / 2);

    {
        const unsigned* gwh = (const unsigned*)Wh;
        const unsigned* gwl = (const unsigned*)Wl;
        for (int i = tid; i < F * 64; i += 256) {
            int r = i >> 6, c = i & 63;
            ((unsigned*)(sWh + r * KPAD))[c] = gwh[i];
            ((unsigned*)(sWl + r * KPAD))[c] = gwl[i];
        }
    }

    int ntiles = (n + 127) >> 7;
    for (int tile = blockIdx.x; tile < ntiles; tile += gridDim.x) {
        __syncthreads();
        int r0 = tile * 128;

        for (int i = tid; i < 4096; i += 256) {
            int r = i >> 5, c4 = i & 31;
            int row = r0 + r;
            float4 v = make_float4(0.f, 0.f, 0.f, 0.f);
            if (row < n) v = *(const float4*)(A + (size_t)row * 128 + c4 * 4);
            if (RELU) {
                v.x = fmaxf(v.x, 0.f); v.y = fmaxf(v.y, 0.f);
                v.z = fmaxf(v.z, 0.f); v.w = fmaxf(v.w, 0.f);
            }
            __nv_bfloat16 h0 = __float2bfloat16(v.x), h1 = __float2bfloat16(v.y);
            __nv_bfloat16 h2 = __float2bfloat16(v.z), h3 = __float2bfloat16(v.w);
            float l0 = v.x - __bfloat162float(h0), l1 = v.y - __bfloat162float(h1);
            float l2 = v.z - __bfloat162float(h2), l3 = v.w - __bfloat162float(h3);
            unsigned h01, h23;
            { __nv_bfloat162 p0 = {h0, h1}; h01 = *reinterpret_cast<unsigned*>(&p0);
              __nv_bfloat162 p1 = {h2, h3}; h23 = *reinterpret_cast<unsigned*>(&p1); }
            unsigned l01 = packbf(l0, l1), l23 = packbf(l2, l3);
            *reinterpret_cast<uint2*>(sAh + r * KPAD + c4 * 4) = make_uint2(h01, h23);
            *reinterpret_cast<uint2*>(sAl + r * KPAD + c4 * 4) = make_uint2(l01, l23);
        }
        __syncthreads();

        float acc[2][NT][4];
        #pragma unroll
        for (int rb = 0; rb < 2; rb++)
            #pragma unroll
            for (int j = 0; j < NT; j++) {
                acc[rb][j][0] = 0.f; acc[rb][j][1] = 0.f;
                acc[rb][j][2] = 0.f; acc[rb][j][3] = 0.f;
            }

        #pragma unroll
        for (int kk = 0; kk < 128; kk += 16) {
            unsigned ah[2][4], al[2][4];
            #pragma unroll
            for (int rb = 0; rb < 2; rb++) {
                int br = arow + rb * 16;
                ah[rb][0] = *(const unsigned*)(sAh + (br + g)     * KPAD + kk + 2 * t);
                ah[rb][1] = *(const unsigned*)(sAh + (br + g + 8) * KPAD + kk + 2 * t);
                ah[rb][2] = *(const unsigned*)(sAh + (br + g)     * KPAD + kk + 8 + 2 * t);
                ah[rb][3] = *(const unsigned*)(sAh + (br + g + 8) * KPAD + kk + 8 + 2 * t);
                al[rb][0] = *(const unsigned*)(sAl + (br + g)     * KPAD + kk + 2 * t);
                al[rb][1] = *(const unsigned*)(sAl + (br + g + 8) * KPAD + kk + 2 * t);
                al[rb][2] = *(const unsigned*)(sAl + (br + g)     * KPAD + kk + 8 + 2 * t);
                al[rb][3] = *(const unsigned*)(sAl + (br + g + 8) * KPAD + kk + 8 + 2 * t);
            }
            #pragma unroll
            for (int j = 0; j < NT; j++) {
                int bn = bcol0 + j * 8 + g;
                unsigned b0h = *(const unsigned*)(sWh + bn * KPAD + kk + 2 * t);
                unsigned b1h = *(const unsigned*)(sWh + bn * KPAD + kk + 8 + 2 * t);
                unsigned b0l = *(const unsigned*)(sWl + bn * KPAD + kk + 2 * t);
                unsigned b1l = *(const unsigned*)(sWl + bn * KPAD + kk + 8 + 2 * t);
                #pragma unroll
                for (int rb = 0; rb < 2; rb++) {
                    mma_bf16(acc[rb][j], ah[rb][0], ah[rb][1], ah[rb][2], ah[rb][3], b0h, b1h);
                    mma_bf16(acc[rb][j], ah[rb][0], ah[rb][1], ah[rb][2], ah[rb][3], b0l, b1l);
                    mma_bf16(acc[rb][j], al[rb][0], al[rb][1], al[rb][2], al[rb][3], b0h, b1h);
                }
            }
        }

        // epilogue: scale by dinv[row], write Y as fp16
        #pragma unroll
        for (int rb = 0; rb < 2; rb++) {
            int row0 = r0 + arow + rb * 16 + g;
            int row1 = row0 + 8;
            float d0 = (row0 < n) ? g_dinv[row0] : 0.f;
            float d1 = (row1 < n) ? g_dinv[row1] : 0.f;
            #pragma unroll
            for (int j = 0; j < NT; j++) {
                int col = bcol0 + j * 8 + 2 * t;
                if (row0 < n) {
                    __half2 p = __floats2half2_rn(acc[rb][j][0] * d0, acc[rb][j][1] * d0);
                    *(__half2*)(g_Y16 + (size_t)row0 * F + col) = p;
                }
                if (row1 < n) {
                    __half2 p = __floats2half2_rn(acc[rb][j][2] * d1, acc[rb][j][3] * d1);
                    *(__half2*)(g_Y16 + (size_t)row1 * F + col) = p;
                }
            }
        }
    }
}

// ---------------- aggregation ------------------------------------------------
// out[i] = dinv[i]*(Y[i] + sum Y[src]) + b
// fp16 gather via read-only path (__ldg); 4 staged rows reduced by an fp16
// pairwise tree, root accumulated fp32. Tail/self-loop exact fp32.
__device__ __forceinline__ __half2 H2(unsigned u) {
    return *reinterpret_cast<__half2*>(&u);
}

__device__ __forceinline__ void acc8(float* a, uint4 r) {
    float2 f0 = __half22float2(H2(r.x));
    float2 f1 = __half22float2(H2(r.y));
    float2 f2 = __half22float2(H2(r.z));
    float2 f3 = __half22float2(H2(r.w));
    a[0] += f0.x; a[1] += f0.y; a[2] += f1.x; a[3] += f1.y;
    a[4] += f2.x; a[5] += f2.y; a[6] += f3.x; a[7] += f3.y;
}

template <int F>
__global__ __launch_bounds__(256)
void agg_k(const float* __restrict__ bias, float* __restrict__ out, int n) {
    const int L = F / 8;                               // lanes per node (16 / 8)
    int lane = threadIdx.x & (L - 1);
    int node = (blockIdx.x * blockDim.x + threadIdx.x) / L;
    if (node >= n) return;

    unsigned mask = ((L == 32) ? 0xffffffffu
                               : (((1u << L) - 1u) << (((threadIdx.x & 31) / L) * L)));

    int s = __ldg(&g_rowptr[node]);
    int e = __ldg(&g_rowptr[node + 1]);

    const __half* Yb = g_Y16;                          // 32-bit offsets suffice
    unsigned loff = lane * 8;

    float a[8];
    {
        uint4 r = __ldg((const uint4*)(Yb + (unsigned)node * F + loff));  // self loop
        #pragma unroll
        for (int q = 0; q < 8; q++) a[q] = 0.f;
        acc8(a, r);
    }

    for (int base = s; base < e; base += L) {
        int idx = base + lane;
        int v = (idx < e) ? __ldg(&g_csrc[idx]) : 0;
        int cnt = min(L, e - base);
        int tt = 0;
        for (; tt + 4 <= cnt; tt += 4) {
            unsigned s0 = (unsigned)__shfl_sync(mask, v, tt,     L) * F + loff;
            unsigned s1 = (unsigned)__shfl_sync(mask, v, tt + 1, L) * F + loff;
            unsigned s2 = (unsigned)__shfl_sync(mask, v, tt + 2, L) * F + loff;
            unsigned s3 = (unsigned)__shfl_sync(mask, v, tt + 3, L) * F + loff;
            uint4 r0 = __ldg((const uint4*)(Yb + s0));
            uint4 r1 = __ldg((const uint4*)(Yb + s1));
            uint4 r2 = __ldg((const uint4*)(Yb + s2));
            uint4 r3 = __ldg((const uint4*)(Yb + s3));
            // fp16 pairwise tree per half2 component, fp32 accumulate of root
            #pragma unroll
            for (int c = 0; c < 4; c++) {
                __half2 t01 = __hadd2(H2((&r0.x)[c]), H2((&r1.x)[c]));
                __half2 t23 = __hadd2(H2((&r2.x)[c]), H2((&r3.x)[c]));
                __half2 tr  = __hadd2(t01, t23);
                float2 f = __half22float2(tr);
                a[c * 2 + 0] += f.x;
                a[c * 2 + 1] += f.y;
            }
        }
        for (; tt < cnt; tt++) {
            unsigned sc = (unsigned)__shfl_sync(mask, v, tt, L) * F + loff;
            uint4 r = __ldg((const uint4*)(Yb + sc));
            acc8(a, r);
        }
    }

    float d = g_dinv[node];
    float4 b0 = *(const float4*)(bias + loff);
    float4 b1 = *(const float4*)(bias + loff + 4);
    float o[8];
    #pragma unroll
    for (int q = 0; q < 8; q++) o[q] = a[q] * d;
    o[0] += b0.x; o[1] += b0.y; o[2] += b0.z; o[3] += b0.w;
    o[4] += b1.x; o[5] += b1.y; o[6] += b1.z; o[7] += b1.w;
    *(float4*)(out + (size_t)node * F + loff)     = make_float4(o[0], o[1], o[2], o[3]);
    *(float4*)(out + (size_t)node * F + loff + 4) = make_float4(o[4], o[5], o[6], o[7]);
}

// ---------------- launch -----------------------------------------------------

extern "C" void kernel_launch(void* const* d_in, const int* in_sizes, int n_in,
                              void* d_out, int out_size) {
    const float* x  = (const float*)d_in[0];
    const int*   ei = (const int*)d_in[1];   // int32
    const float* W1 = (const float*)d_in[2];
    const float* b1 = (const float*)d_in[3];
    const float* W2 = (const float*)d_in[4];
    const float* b2 = (const float*)d_in[5];
    const float* W3 = (const float*)d_in[6];
    const float* b3 = (const float*)d_in[7];
    float* out = (float*)d_out;

    float* hH = nullptr;
    cudaGetSymbolAddress((void**)&hH, g_H);
    __nv_bfloat16 *w1h, *w1l, *w2h, *w2l, *w3h, *w3l;
    cudaGetSymbolAddress((void**)&w1h, g_W1h);
    cudaGetSymbolAddress((void**)&w1l, g_W1l);
    cudaGetSymbolAddress((void**)&w2h, g_W2h);
    cudaGetSymbolAddress((void**)&w2l, g_W2l);
    cudaGetSymbolAddress((void**)&w3h, g_W3h);
    cudaGetSymbolAddress((void**)&w3l, g_W3l);

    int n = in_sizes[0] / 128;
    int E = in_sizes[1] / 2;

    const int SMEM128 = 4 * KPAD * (128 + 128);  // 139264 B
    const int SMEM64  = 4 * KPAD * (64  + 128);  // 104448 B
    cudaFuncSetAttribute(gemm_tc<128, false>, cudaFuncAttributeMaxDynamicSharedMemorySize, SMEM128);
    cudaFuncSetAttribute(gemm_tc<128, true>,  cudaFuncAttributeMaxDynamicSharedMemorySize, SMEM128);
    cudaFuncSetAttribute(gemm_tc<64,  true>,  cudaFuncAttributeMaxDynamicSharedMemorySize, SMEM64);

    // side stream + events (created once on the un-captured correctness call)
    static cudaStream_t sB = nullptr;
    static cudaEvent_t  evF = nullptr, evD = nullptr, evJ = nullptr;
    if (sB == nullptr) {
        cudaStreamCreateWithFlags(&sB, cudaStreamNonBlocking);
        cudaEventCreateWithFlags(&evF, cudaEventDisableTiming);
        cudaEventCreateWithFlags(&evD, cudaEventDisableTiming);
        cudaEventCreateWithFlags(&evJ, cudaEventDisableTiming);
    }

    int nbE  = (E + 255) / 256;
    int nbE2 = (E / 2 + 255) / 256;            // 2 edges per thread (fill)
    int nbS  = (n + 1023) / 1024;              // 49 <= 64

    // ---- fork ----
    cudaEventRecord(evF, 0);
    cudaStreamWaitEvent(sB, evF, 0);

    // main stream: CSR chain (critical path for agg1)
    count_k<<<nbE, 256>>>(ei, E);               // + epos
    scan_partial_k<<<nbS, 1024>>>(n);           // produces dinv
    cudaEventRecord(evD, 0);                    // dinv ready
    scan_final_k<<<nbS, 1024>>>(n, nbS);
    fill_k<<<nbE2, 256>>>(ei, E);               // atomic-free, 2-edge ILP

    // stream B: weights + gemm1 (epilogue needs dinv -> waits evD)
    convW_all_k<<<160, 256, 0, sB>>>(W1, W2, W3);
    cudaStreamWaitEvent(sB, evD, 0);
    gemm_tc<128, false><<<148, 256, SMEM128, sB>>>(x, w1h, w1l, n);
    cudaEventRecord(evJ, sB);

    // ---- join ----
    cudaStreamWaitEvent(0, evJ, 0);

    int gAgg128 = ((n * 16) + 255) / 256;   // L=16 lanes per node
    int gAgg64  = ((n * 8)  + 255) / 256;   // L=8

    agg_k<128><<<gAgg128, 256>>>(b1, hH, n);

    gemm_tc<128, true><<<148, 256, SMEM128>>>(hH, w2h, w2l, n);
    agg_k<128><<<gAgg128, 256>>>(b2, hH, n);

    gemm_tc<64, true><<<296, 256, SMEM64>>>(hH, w3h, w3l, n);
    agg_k<64><<<gAgg64, 256>>>(b3, out, n);
}